// round 11
// baseline (speedup 1.0000x reference)
#include <cuda_runtime.h>
#include <cstdint>

// CSR SpMM, sum-reduce: out[r,:] = sum_e value[e] * other[col[e],:]
// N_ROWS=100000, DEG=16 (fixed), F=64, fp32. rowptr/col INT32.
//
// Model (R3-R7): all designs saturate the chip LTS path (~455MB of L2 traffic
// in ~29us ~= 15.7TB/s ~= the measured path-independent LTS cap). Occupancy,
// MLP, and load shape are no longer levers; only overhead trims remain.
// R10 = R5's best structure + trims:
//  - __ldcg gathers (no L1 alloc), __ldcs streaming metadata
//  - 32-bit unsigned gather offsets (c*16+f <= 1.6M fits; kills 64-bit chains)
//  - launch_bounds(256,6)

static constexpr int F4 = 16;       // float4 groups per row (F=64)
static constexpr int ROWS_PER_BLK = 16;

__global__ __launch_bounds__(256, 6) void spmm_kernel(
    const int* __restrict__ rowptr,
    const int* __restrict__ col,
    const float* __restrict__ value,
    const float4* __restrict__ other,   // [N_COLS * 16] float4
    float4* __restrict__ out,           // [N_ROWS * 16] float4
    int n_rows)
{
    const int row = blockIdx.x * ROWS_PER_BLK + threadIdx.y;
    if (row >= n_rows) return;
    const unsigned f = threadIdx.x;     // 0..15

    const int start = rowptr[row];
    const int deg   = rowptr[row + 1] - start;

    float4 acc = make_float4(0.f, 0.f, 0.f, 0.f);

    if (deg == 16 && (start & 3) == 0) {
        const int4*   c4 = (const int4*)(col + start);
        const float4* v4 = (const float4*)(value + start);

        // Metadata pre-resident (R5 style; broadcast within the 16-lane group,
        // streaming hint so it doesn't displace `other` in L2).
        int4   c[4];
        float4 v[4];
#pragma unroll
        for (int b = 0; b < 4; ++b) {
            c[b] = __ldcs(&c4[b]);
            v[b] = __ldcs(&v4[b]);
        }

#pragma unroll
        for (int b = 0; b < 4; ++b) {
            // 32-bit unsigned offsets: max = 99999*16+15 < 2^21.
            const unsigned o0 = (unsigned)c[b].x * 16u + f;
            const unsigned o1 = (unsigned)c[b].y * 16u + f;
            const unsigned o2 = (unsigned)c[b].z * 16u + f;
            const unsigned o3 = (unsigned)c[b].w * 16u + f;

            float4 x0 = __ldcg(other + o0);
            float4 x1 = __ldcg(other + o1);
            float4 x2 = __ldcg(other + o2);
            float4 x3 = __ldcg(other + o3);

            acc.x = fmaf(v[b].x, x0.x, acc.x);
            acc.y = fmaf(v[b].x, x0.y, acc.y);
            acc.z = fmaf(v[b].x, x0.z, acc.z);
            acc.w = fmaf(v[b].x, x0.w, acc.w);

            acc.x = fmaf(v[b].y, x1.x, acc.x);
            acc.y = fmaf(v[b].y, x1.y, acc.y);
            acc.z = fmaf(v[b].y, x1.z, acc.z);
            acc.w = fmaf(v[b].y, x1.w, acc.w);

            acc.x = fmaf(v[b].z, x2.x, acc.x);
            acc.y = fmaf(v[b].z, x2.y, acc.y);
            acc.z = fmaf(v[b].z, x2.z, acc.z);
            acc.w = fmaf(v[b].z, x2.w, acc.w);

            acc.x = fmaf(v[b].w, x3.x, acc.x);
            acc.y = fmaf(v[b].w, x3.y, acc.y);
            acc.z = fmaf(v[b].w, x3.z, acc.z);
            acc.w = fmaf(v[b].w, x3.w, acc.w);
        }
    } else {
        for (int e = start; e < start + deg; ++e) {
            const int   c = __ldg(&col[e]);
            const float v = __ldg(&value[e]);
            const float4 x = __ldcg(&other[(unsigned)c * 16u + f]);
            acc.x = fmaf(v, x.x, acc.x);
            acc.y = fmaf(v, x.y, acc.y);
            acc.z = fmaf(v, x.z, acc.z);
            acc.w = fmaf(v, x.w, acc.w);
        }
    }

    out[(unsigned)row * 16u + f] = acc;
}

extern "C" void kernel_launch(void* const* d_in, const int* in_sizes, int n_in,
                              void* d_out, int out_size)
{
    // metadata order: rowptr (int32, N_ROWS+1), col (int32, E), value (f32, E), other (f32, N_COLS*F)
    const int*    rowptr = (const int*)d_in[0];
    const int*    col    = (const int*)d_in[1];
    const float*  value  = (const float*)d_in[2];
    const float4* other  = (const float4*)d_in[3];
    float4*       out    = (float4*)d_out;

    const int n_rows = in_sizes[0] - 1;

    dim3 block(F4, ROWS_PER_BLK);
    dim3 grid((n_rows + ROWS_PER_BLK - 1) / ROWS_PER_BLK);
    spmm_kernel<<<grid, block>>>(rowptr, col, value, other, out, n_rows);
}